// round 11
// baseline (speedup 1.0000x reference)
#include <cuda_runtime.h>
#include <cstdint>

#define M_DIM 256
#define I_DIM 512
#define D_DIM 128
#define H_DIM 128
#define NBLK  1024
#define NWAVE 4
#define RPW   128            // rows per wave
#define ZSPLIT 8             // partial blocks per row
#define M_PER 32             // m's per partial block

// Scratch (device globals; zero-initialized; no allocation allowed)
__device__ float g_part[ZSPLIT * I_DIM * D_DIM];   // 2 MB partials
__device__ float g_L[I_DIM * D_DIM];
__device__ float g_R[I_DIM * D_DIM];
__device__ int   g_cntR[I_DIM];    // per-row arrivals (8); winner resets
__device__ int   g_rdy[NWAVE];     // projected-row count per wave
__device__ int   g_done;           // final arrivals; last resets g_rdy

// map flat unit u of ring Delta_k ([0,128k)^2 \ [0,128(k-1))^2) to (i, junit)
// unit = (row i, 32 consecutive j's). Delta_k has 512*(2k-1) units.
__device__ __forceinline__ void delta_map(int k, int u, int& i, int& junit)
{
    const int a = 512 * (k - 1);          // strip A: i<128(k-1), j in new cols
    if (u < a) {
        i = u >> 2;
        junit = 4 * (k - 1) + (u & 3);
    } else {                              // strip B: new rows, all j<128k
        const int v = u - a;
        const int wdt = 4 * k;
        i = 128 * (k - 1) + v / wdt;
        junit = v % wdt;
    }
}

__device__ __forceinline__ void write_unit(
    float4* __restrict__ o4, int i, int junit, int d4, int jl)
{
    const float4* __restrict__ L4 = reinterpret_cast<const float4*>(g_L);
    const float4* __restrict__ R4 = reinterpret_cast<const float4*>(g_R);
    const float4 Lv = __ldg(&L4[i * 32 + d4]);
    #pragma unroll
    for (int p = 0; p < 4; p++) {
        const int j = junit * 32 + jl + p * 8;
        const float4 Rv = __ldg(&R4[j * 32 + d4]);
        float4 o;
        o.x = Lv.x + Rv.x; o.y = Lv.y + Rv.y;
        o.z = Lv.z + Rv.z; o.w = Lv.w + Rv.w;
        __stcs(&o4[((size_t)i * I_DIM + j) * 32 + d4], o);
    }
}

__device__ __forceinline__ void spin_waves(int upto)  // wait waves [0,upto] done
{
    for (int k = 0; k <= upto; k++)
        while (*(volatile int*)&g_rdy[k] < RPW) __nanosleep(64);
}

__global__ void __launch_bounds__(256, 7) fused_kernel(
    const float* __restrict__ x,
    const float* __restrict__ ln_g, const float* __restrict__ ln_b,
    const float* __restrict__ wl, const float* __restrict__ bl,
    const float* __restrict__ wr, const float* __restrict__ br,
    const float* __restrict__ wo, const float* __restrict__ bo,
    float* __restrict__ out)
{
    const int tid  = threadIdx.x;
    const int bid  = blockIdx.x;
    const int warp = tid >> 5;
    const int lane = tid & 31;
    const int rrow = bid >> 3;   // row index within wave (0..127)
    const int z    = bid & 7;    // m-partial index (0..7)
    const int d4   = tid & 31;   // write helpers
    const int jl   = tid >> 5;

    const float4* __restrict__ x4 = reinterpret_cast<const float4*>(x);
    float4* __restrict__ o4 = reinterpret_cast<float4*>(out);

    __shared__ float part[8][D_DIM];
    __shared__ float xs[D_DIM], ls[H_DIM], rs[H_DIM];
    __shared__ int s_win;

    #pragma unroll 1
    for (int w = 0; w < NWAVE; w++) {
        const int i = w * RPW + rrow;

        // ---- read 32 m's (4 per warp), LN, accumulate (v-mu)*rstd ----
        float4 v[4];
        #pragma unroll
        for (int u = 0; u < 4; u++) {
            const int m = z * M_PER + u * 8 + warp;
            v[u] = x4[((size_t)m * I_DIM + i) * 32 + lane];
        }
        float s[4], sq[4];
        #pragma unroll
        for (int u = 0; u < 4; u++) {
            s[u]  = v[u].x + v[u].y + v[u].z + v[u].w;
            sq[u] = v[u].x*v[u].x + v[u].y*v[u].y
                  + v[u].z*v[u].z + v[u].w*v[u].w;
        }
        #pragma unroll
        for (int o = 16; o; o >>= 1) {
            #pragma unroll
            for (int u = 0; u < 4; u++) {
                s[u]  += __shfl_xor_sync(0xffffffffu, s[u],  o);
                sq[u] += __shfl_xor_sync(0xffffffffu, sq[u], o);
            }
        }
        float a0 = 0.f, a1 = 0.f, a2 = 0.f, a3 = 0.f;
        #pragma unroll
        for (int u = 0; u < 4; u++) {
            const float mu   = s[u] * (1.f / 128.f);
            const float var  = sq[u] * (1.f / 128.f) - mu * mu;
            const float rstd = rsqrtf(var + 1e-5f);
            a0 += (v[u].x - mu) * rstd;
            a1 += (v[u].y - mu) * rstd;
            a2 += (v[u].z - mu) * rstd;
            a3 += (v[u].w - mu) * rstd;
        }

        part[warp][lane * 4 + 0] = a0;
        part[warp][lane * 4 + 1] = a1;
        part[warp][lane * 4 + 2] = a2;
        part[warp][lane * 4 + 3] = a3;
        __syncthreads();

        if (tid < D_DIM) {
            float sum = 0.f;
            #pragma unroll
            for (int ww = 0; ww < 8; ww++) sum += part[ww][tid];
            g_part[((size_t)z * I_DIM + i) * D_DIM + tid] = sum;
            __threadfence();
        }
        __syncthreads();

        // ---- arrive on row; 8th arriver projs the row ----
        if (tid == 0) {
            const int old = atomicAdd(&g_cntR[i], 1);
            s_win = (old == ZSPLIT - 1);
            if (s_win) {
                g_cntR[i] = 0;     // reset for next replay
                __threadfence();   // acquire the other 7 partials
            }
        }
        __syncthreads();

        if (s_win) {
            const int h    = tid & 127;
            const int side = tid >> 7;
            if (tid < D_DIM) {
                float sum = 0.f;
                #pragma unroll
                for (int zz = 0; zz < ZSPLIT; zz++)
                    sum += g_part[((size_t)zz * I_DIM + i) * D_DIM + tid];
                xs[tid] = sum * (1.f / (float)M_DIM) * ln_g[tid] + ln_b[tid];
            }
            __syncthreads();
            {   // stage 1
                const float* __restrict__ w1 = side ? wr : wl;
                float acc = side ? br[h] : bl[h];
                #pragma unroll 8
                for (int c = 0; c < D_DIM; c++)
                    acc += xs[c] * w1[c * H_DIM + h];
                if (side) rs[h] = acc; else ls[h] = acc;
            }
            __syncthreads();
            {   // stage 2
                const float* __restrict__ vv = side ? rs : ls;
                float acc = side ? bo[h] : 0.f;
                #pragma unroll 8
                for (int c = 0; c < H_DIM; c++)
                    acc += vv[c] * wo[c * D_DIM + h];
                if (side) g_R[i * D_DIM + h] = acc;
                else      g_L[i * D_DIM + h] = acc;
            }
            __threadfence();
            __syncthreads();
            if (tid == 0) atomicAdd(&g_rdy[w], 1);
            __syncthreads();
        }

        // ---- write the ring Delta_w enabled by waves [0, w-1] ----
        if (w >= 1) {
            if (tid == 0) spin_waves(w - 1);
            __syncthreads();
            const int cnt = 512 * (2 * w - 1);
            #pragma unroll 1
            for (int u = bid; u < cnt; u += NBLK) {
                int ii, ju;
                delta_map(w, u, ii, ju);
                write_unit(o4, ii, ju, d4, jl);
            }
        }
        __syncthreads();   // protect smem reuse for next wave
    }

    // ---- final ring Delta_4 (needs all waves) ----
    if (tid == 0) spin_waves(NWAVE - 1);
    __syncthreads();
    {
        const int cnt = 512 * (2 * NWAVE - 1);   // 3584
        #pragma unroll 1
        for (int u = bid; u < cnt; u += NBLK) {
            int ii, ju;
            delta_map(NWAVE, u, ii, ju);
            write_unit(o4, ii, ju, d4, jl);
        }
    }

    // ---- epilogue: last block resets wave counters for next replay ----
    __syncthreads();
    if (tid == 0) {
        const int old = atomicAdd(&g_done, 1);
        if (old == NBLK - 1) {
            #pragma unroll
            for (int k = 0; k < NWAVE; k++) g_rdy[k] = 0;
            g_done = 0;
            __threadfence();
        }
    }
}

// ---------------------------------------------------------------------------
extern "C" void kernel_launch(void* const* d_in, const int* in_sizes, int n_in,
                              void* d_out, int out_size)
{
    const float* x    = (const float*)d_in[0];
    const float* ln_g = (const float*)d_in[1];
    const float* ln_b = (const float*)d_in[2];
    const float* wl   = (const float*)d_in[3];
    const float* bl   = (const float*)d_in[4];
    const float* wr   = (const float*)d_in[5];
    const float* br   = (const float*)d_in[6];
    const float* wo   = (const float*)d_in[7];
    const float* bo   = (const float*)d_in[8];
    float* out = (float*)d_out;

    fused_kernel<<<NBLK, 256>>>(x, ln_g, ln_b, wl, bl, wr, br, wo, bo, out);
}

// round 14
// speedup vs baseline: 1.4338x; 1.4338x over previous
#include <cuda_runtime.h>
#include <cstdint>

#define M_DIM 256
#define I_DIM 512
#define D_DIM 128
#define H_DIM 128
#define NBLK  1024

// Scratch (device globals; zero-initialized; no allocation allowed)
__device__ float g_part[4 * I_DIM * D_DIM];
__device__ float g_L[I_DIM * D_DIM];
__device__ float g_R[I_DIM * D_DIM];
__device__ int   g_cntR[I_DIM];   // per-row arrivals; winner resets
__device__ int   g_rdy1;          // rows [256,512) projected (kernel 2)
__device__ int   g_done;          // kernel-2 epilogue; last resets g_rdy1

// ---------------- write one (row i, 32 consecutive j) unit ----------------
__device__ __forceinline__ void write_unit(
    float4* __restrict__ o4, int i, int junit, int d4, int jl)
{
    const float4* __restrict__ L4 = reinterpret_cast<const float4*>(g_L);
    const float4* __restrict__ R4 = reinterpret_cast<const float4*>(g_R);
    const float4 Lv = __ldcg(&L4[i * 32 + d4]);
    #pragma unroll
    for (int p = 0; p < 4; p++) {
        const int j = junit * 32 + jl + p * 8;
        const float4 Rv = __ldcg(&R4[j * 32 + d4]);
        float4 o;
        o.x = Lv.x + Rv.x; o.y = Lv.y + Rv.y;
        o.z = Lv.z + Rv.z; o.w = Lv.w + Rv.w;
        __stcs(&o4[((size_t)i * I_DIM + j) * 32 + d4], o);
    }
}

// ---- LN partial: nt32*32 m's starting at m_base -> g_part[slot][i][:] ----
__device__ __forceinline__ void ln_partial(
    const float4* __restrict__ x4, int i, int m_base, int slot, int nt32,
    int warp, int lane, int tid, float (*part)[D_DIM])
{
    float a0 = 0.f, a1 = 0.f, a2 = 0.f, a3 = 0.f;
    #pragma unroll 1
    for (int t = 0; t < nt32; t++) {
        float4 v[4];
        #pragma unroll
        for (int u = 0; u < 4; u++) {
            const int m = m_base + warp + (t * 4 + u) * 8;
            v[u] = x4[((size_t)m * I_DIM + i) * 32 + lane];
        }
        float s[4], sq[4];
        #pragma unroll
        for (int u = 0; u < 4; u++) {
            s[u]  = v[u].x + v[u].y + v[u].z + v[u].w;
            sq[u] = v[u].x*v[u].x + v[u].y*v[u].y
                  + v[u].z*v[u].z + v[u].w*v[u].w;
        }
        #pragma unroll
        for (int o = 16; o; o >>= 1) {
            #pragma unroll
            for (int u = 0; u < 4; u++) {
                s[u]  += __shfl_xor_sync(0xffffffffu, s[u],  o);
                sq[u] += __shfl_xor_sync(0xffffffffu, sq[u], o);
            }
        }
        #pragma unroll
        for (int u = 0; u < 4; u++) {
            const float mu   = s[u] * (1.f / 128.f);
            const float var  = sq[u] * (1.f / 128.f) - mu * mu;
            const float rstd = rsqrtf(var + 1e-5f);
            a0 += (v[u].x - mu) * rstd;
            a1 += (v[u].y - mu) * rstd;
            a2 += (v[u].z - mu) * rstd;
            a3 += (v[u].w - mu) * rstd;
        }
    }
    part[warp][lane * 4 + 0] = a0;
    part[warp][lane * 4 + 1] = a1;
    part[warp][lane * 4 + 2] = a2;
    part[warp][lane * 4 + 3] = a3;
    __syncthreads();
    if (tid < D_DIM) {
        float sum = 0.f;
        #pragma unroll
        for (int w = 0; w < 8; w++) sum += part[w][tid];
        g_part[((size_t)slot * I_DIM + i) * D_DIM + tid] = sum;
        __threadfence();
    }
    __syncthreads();
}

// ------------- proj chain for row i (nslot partials); 256 thr -------------
__device__ __forceinline__ void proj_row(
    int i, int nslot,
    const float* __restrict__ ln_g, const float* __restrict__ ln_b,
    const float* __restrict__ wl, const float* __restrict__ bl,
    const float* __restrict__ wr, const float* __restrict__ br,
    const float* __restrict__ wo, const float* __restrict__ bo,
    int tid, float* xs, float* ls, float* rs)
{
    const int h    = tid & 127;
    const int side = tid >> 7;
    if (tid < D_DIM) {
        float sum = 0.f;
        for (int z = 0; z < nslot; z++)
            sum += g_part[((size_t)z * I_DIM + i) * D_DIM + tid];
        xs[tid] = sum * (1.f / (float)M_DIM) * ln_g[tid] + ln_b[tid];
    }
    __syncthreads();
    {
        const float* __restrict__ w1 = side ? wr : wl;
        float acc = side ? br[h] : bl[h];
        #pragma unroll 8
        for (int c = 0; c < D_DIM; c++)
            acc += xs[c] * w1[c * H_DIM + h];
        if (side) rs[h] = acc; else ls[h] = acc;
    }
    __syncthreads();
    {
        const float* __restrict__ vv = side ? rs : ls;
        float acc = side ? bo[h] : 0.f;
        #pragma unroll 8
        for (int c = 0; c < H_DIM; c++)
            acc += vv[c] * wo[c * D_DIM + h];
        if (side) g_R[i * D_DIM + h] = acc;
        else      g_L[i * D_DIM + h] = acc;
    }
    __threadfence();
    __syncthreads();
}

// ============ Kernel 1: rows [0,256) — LN + proj, no global sync ============
__global__ void __launch_bounds__(256, 7) k1_firsthalf(
    const float* __restrict__ x,
    const float* __restrict__ ln_g, const float* __restrict__ ln_b,
    const float* __restrict__ wl, const float* __restrict__ bl,
    const float* __restrict__ wr, const float* __restrict__ br,
    const float* __restrict__ wo, const float* __restrict__ bo)
{
    const int tid  = threadIdx.x;
    const int bid  = blockIdx.x;
    const int warp = tid >> 5;
    const int lane = tid & 31;
    const int i = bid >> 2;          // 0..255
    const int z = bid & 3;           // 4 partials/row, 64 m's each

    __shared__ float part[8][D_DIM];
    __shared__ float xs[D_DIM], ls[H_DIM], rs[H_DIM];
    __shared__ int s_win;

    ln_partial(reinterpret_cast<const float4*>(x), i, z * 64, z, 2,
               warp, lane, tid, part);

    if (tid == 0) {
        const int old = atomicAdd(&g_cntR[i], 1);
        s_win = (old == 3);
        if (s_win) { g_cntR[i] = 0; __threadfence(); }
    }
    __syncthreads();
    if (s_win)
        proj_row(i, 4, ln_g, ln_b, wl, bl, wr, br, wo, bo, tid, xs, ls, rs);
}

// ===== Kernel 2: rows [256,512) LN+proj  ||  Q00 writes; then the rest =====
__global__ void __launch_bounds__(256, 7) k2_overlap(
    const float* __restrict__ x,
    const float* __restrict__ ln_g, const float* __restrict__ ln_b,
    const float* __restrict__ wl, const float* __restrict__ bl,
    const float* __restrict__ wr, const float* __restrict__ br,
    const float* __restrict__ wo, const float* __restrict__ bo,
    float* __restrict__ out)
{
    const int tid  = threadIdx.x;
    const int bid  = blockIdx.x;
    const int warp = tid >> 5;
    const int lane = tid & 31;
    const int d4   = tid & 31;
    const int jl   = tid >> 5;
    float4* __restrict__ o4 = reinterpret_cast<float4*>(out);

    __shared__ float part[8][D_DIM];
    __shared__ float xs[D_DIM], ls[H_DIM], rs[H_DIM];
    __shared__ int s_win;

    if (bid < 512) {
        // readers: rows [256,512), 2 blocks/row, 128 m's each
        const int i = 256 + (bid >> 1);
        const int z = bid & 1;
        ln_partial(reinterpret_cast<const float4*>(x), i, z * 128, z, 4,
                   warp, lane, tid, part);
        if (tid == 0) {
            const int old = atomicAdd(&g_cntR[i], 1);
            s_win = (old == 1);
            if (s_win) { g_cntR[i] = 0; __threadfence(); }
        }
        __syncthreads();
        if (s_win) {
            proj_row(i, 2, ln_g, ln_b, wl, bl, wr, br, wo, bo, tid, xs, ls, rs);
            if (tid == 0) atomicAdd(&g_rdy1, 1);
            __syncthreads();
        }
    } else {
        // early writers: Q00 (i<256, j<256); deps done in kernel 1
        const int c = bid - 512;
        #pragma unroll
        for (int k = 0; k < 4; k++) {
            const int u = c * 4 + k;             // 2048 units
            write_unit(o4, u >> 3, u & 7, d4, jl);
        }
    }

    // wait for rows [256,512); rows [0,256) guaranteed by kernel boundary
    if (tid == 0) {
        while (*(volatile int*)&g_rdy1 < 256) __nanosleep(128);
    }
    __syncthreads();

    // remaining 3 quadrants: 6144 units, 6 per block
    #pragma unroll
    for (int k = 0; k < 6; k++) {
        const int g = bid * 6 + k;
        const int q = g >> 11;
        const int r = g & 2047;
        int i, junit;
        if (q == 0)      { i = r >> 3;         junit = 8 + (r & 7); }
        else if (q == 1) { i = 256 + (r >> 3); junit = r & 7; }
        else             { i = 256 + (r >> 3); junit = 8 + (r & 7); }
        write_unit(o4, i, junit, d4, jl);
    }

    // epilogue: last block resets counters for next graph replay
    __syncthreads();
    if (tid == 0) {
        const int old = atomicAdd(&g_done, 1);
        if (old == NBLK - 1) {
            g_rdy1 = 0;
            g_done = 0;
            __threadfence();
        }
    }
}

// ---------------------------------------------------------------------------
extern "C" void kernel_launch(void* const* d_in, const int* in_sizes, int n_in,
                              void* d_out, int out_size)
{
    const float* x    = (const float*)d_in[0];
    const float* ln_g = (const float*)d_in[1];
    const float* ln_b = (const float*)d_in[2];
    const float* wl   = (const float*)d_in[3];
    const float* bl   = (const float*)d_in[4];
    const float* wr   = (const float*)d_in[5];
    const float* br   = (const float*)d_in[6];
    const float* wo   = (const float*)d_in[7];
    const float* bo   = (const float*)d_in[8];
    float* out = (float*)d_out;

    k1_firsthalf<<<NBLK, 256>>>(x, ln_g, ln_b, wl, bl, wr, br, wo, bo);
    k2_overlap<<<NBLK, 256>>>(x, ln_g, ln_b, wl, bl, wr, br, wo, bo, out);
}

// round 16
// speedup vs baseline: 1.6322x; 1.1384x over previous
#include <cuda_runtime.h>
#include <cstdint>

#define M_DIM 256
#define I_DIM 512
#define D_DIM 128
#define H_DIM 128
#define NBLK  1024           // (512 rows) x (2 m-halves); all co-resident

// Scratch (device globals; zero-initialized; no allocation allowed)
__device__ float g_part[2 * I_DIM * D_DIM];
__device__ float g_L[I_DIM * D_DIM];
__device__ float g_R[I_DIM * D_DIM];
__device__ int   g_cntA[I_DIM];   // per-row arrivals (2); winner resets
__device__ int   g_readyRows;     // rows fully projected
__device__ int   g_done;          // broadcast arrivals; last resets globals

__global__ void __launch_bounds__(256, 7) fused_kernel(
    const float* __restrict__ x,
    const float* __restrict__ ln_g, const float* __restrict__ ln_b,
    const float* __restrict__ wl, const float* __restrict__ bl,
    const float* __restrict__ wr, const float* __restrict__ br,
    const float* __restrict__ wo, const float* __restrict__ bo,
    float* __restrict__ out)
{
    const int tid  = threadIdx.x;
    const int i    = blockIdx.x >> 1;   // row
    const int z    = blockIdx.x & 1;    // m-half
    const int warp = tid >> 5;
    const int lane = tid & 31;

    // ================= Phase A: LN partial over 128 m's =================
    {
        const float4* __restrict__ x4 = reinterpret_cast<const float4*>(x);
        float a0 = 0.f, a1 = 0.f, a2 = 0.f, a3 = 0.f;
        const int m_base = z * 128 + warp;

        #pragma unroll 1
        for (int t = 0; t < 16; t += 4) {
            float4 v[4];
            #pragma unroll
            for (int u = 0; u < 4; u++) {
                const int m = m_base + (t + u) * 8;
                v[u] = x4[((size_t)m * I_DIM + i) * 32 + lane];
            }
            float s[4], sq[4];
            #pragma unroll
            for (int u = 0; u < 4; u++) {
                s[u]  = v[u].x + v[u].y + v[u].z + v[u].w;
                sq[u] = v[u].x*v[u].x + v[u].y*v[u].y
                      + v[u].z*v[u].z + v[u].w*v[u].w;
            }
            #pragma unroll
            for (int o = 16; o; o >>= 1) {
                #pragma unroll
                for (int u = 0; u < 4; u++) {
                    s[u]  += __shfl_xor_sync(0xffffffffu, s[u],  o);
                    sq[u] += __shfl_xor_sync(0xffffffffu, sq[u], o);
                }
            }
            #pragma unroll
            for (int u = 0; u < 4; u++) {
                const float mu   = s[u] * (1.f / 128.f);
                const float var  = sq[u] * (1.f / 128.f) - mu * mu;
                const float rstd = rsqrtf(var + 1e-5f);
                a0 += (v[u].x - mu) * rstd;
                a1 += (v[u].y - mu) * rstd;
                a2 += (v[u].z - mu) * rstd;
                a3 += (v[u].w - mu) * rstd;
            }
        }

        __shared__ float part[8][D_DIM];
        part[warp][lane * 4 + 0] = a0;
        part[warp][lane * 4 + 1] = a1;
        part[warp][lane * 4 + 2] = a2;
        part[warp][lane * 4 + 3] = a3;
        __syncthreads();

        if (tid < D_DIM) {
            float sum = 0.f;
            #pragma unroll
            for (int w = 0; w < 8; w++) sum += part[w][tid];
            g_part[((size_t)z * I_DIM + i) * D_DIM + tid] = sum;
            __threadfence();
        }
        __syncthreads();
    }

    // ======= Phase B: last-arriver per row does the proj chain =======
    __shared__ int s_win;
    if (tid == 0) {
        const int old = atomicAdd(&g_cntA[i], 1);
        s_win = (old == 1);
        if (s_win) {
            g_cntA[i] = 0;      // reset for next replay
            __threadfence();    // acquire partner's partial
        }
    }
    __syncthreads();

    if (s_win) {
        const int h    = tid & 127;
        const int side = tid >> 7;
        __shared__ float xs[D_DIM];
        __shared__ float ls[H_DIM], rs[H_DIM];

        if (tid < D_DIM) {
            const float sum = g_part[i * D_DIM + tid]
                            + g_part[(size_t)(I_DIM + i) * D_DIM + tid];
            xs[tid] = sum * (1.f / (float)M_DIM) * ln_g[tid] + ln_b[tid];
        }
        __syncthreads();

        {   // stage 1: lm / rm
            const float* __restrict__ w1 = side ? wr : wl;
            float acc = side ? br[h] : bl[h];
            #pragma unroll 8
            for (int c = 0; c < D_DIM; c++)
                acc += xs[c] * w1[c * H_DIM + h];
            if (side) rs[h] = acc; else ls[h] = acc;
        }
        __syncthreads();
        {   // stage 2: L / R
            const float* __restrict__ v = side ? rs : ls;
            float acc = side ? bo[h] : 0.f;
            #pragma unroll 8
            for (int c = 0; c < H_DIM; c++)
                acc += v[c] * wo[c * D_DIM + h];
            if (side) g_R[i * D_DIM + h] = acc;
            else      g_L[i * D_DIM + h] = acc;
        }
        __threadfence();
        __syncthreads();
        if (tid == 0) atomicAdd(&g_readyRows, 1);
    }

    // ============ Phase C: all blocks broadcast-write ============
    if (tid == 0) {
        while (*(volatile int*)&g_readyRows < I_DIM) __nanosleep(128);
    }
    __syncthreads();

    {
        const int d4 = tid & 31;
        const int jl = tid >> 5;
        const float4* __restrict__ L4 = reinterpret_cast<const float4*>(g_L);
        const float4* __restrict__ R4 = reinterpret_cast<const float4*>(g_R);
        float4* __restrict__ o4 = reinterpret_cast<float4*>(out);

        // 8192 units of (i, 32 j's); 8 contiguous units per block
        #pragma unroll 1
        for (int k = 0; k < 8; k++) {
            const int u  = blockIdx.x * 8 + k;
            const int ui = u >> 4;
            const int j0 = (u & 15) * 32;
            const float4 Lv = __ldg(&L4[ui * 32 + d4]);
            #pragma unroll
            for (int p = 0; p < 4; p++) {
                const int j = j0 + jl + p * 8;
                const float4 Rv = __ldg(&R4[j * 32 + d4]);
                float4 o;
                o.x = Lv.x + Rv.x; o.y = Lv.y + Rv.y;
                o.z = Lv.z + Rv.z; o.w = Lv.w + Rv.w;
                // write-through, no L2 allocation: keep L2 free so x stays
                // warm across graph replays
                __stwt(&o4[((size_t)ui * I_DIM + j) * 32 + d4], o);
            }
        }
    }

    // ============ epilogue: last block resets global counters ============
    __syncthreads();
    if (tid == 0) {
        const int old = atomicAdd(&g_done, 1);
        if (old == NBLK - 1) {
            g_readyRows = 0;
            g_done = 0;
            __threadfence();
        }
    }
}

// ---------------------------------------------------------------------------
extern "C" void kernel_launch(void* const* d_in, const int* in_sizes, int n_in,
                              void* d_out, int out_size)
{
    const float* x    = (const float*)d_in[0];
    const float* ln_g = (const float*)d_in[1];
    const float* ln_b = (const float*)d_in[2];
    const float* wl   = (const float*)d_in[3];
    const float* bl   = (const float*)d_in[4];
    const float* wr   = (const float*)d_in[5];
    const float* br   = (const float*)d_in[6];
    const float* wo   = (const float*)d_in[7];
    const float* bo   = (const float*)d_in[8];
    float* out = (float*)d_out;

    fused_kernel<<<NBLK, 256>>>(x, ln_g, ln_b, wl, bl, wr, br, wo, bo, out);
}